// round 5
// baseline (speedup 1.0000x reference)
#include <cuda_runtime.h>
#include <math_constants.h>

// Problem maxima (fixed by the dataset): B=4, N=20000, E=640000, H=8
#define MAXB 4
#define MAXN 20000
#define MAXE 640000
#define BNMAX (MAXB * MAXN)
#define BEMAX (MAXB * MAXE)

// Scratch (device globals; no dynamic allocation allowed)
__device__ float g_x0 [BNMAX * 3];        // raw node inputs
__device__ float g_pdA[BNMAX * 8];        // node projections, buffer A (dst role)
__device__ float g_psA[BNMAX * 8];        //                            (src role)
__device__ float g_pdB[BNMAX * 8];        // buffer B
__device__ float g_psB[BNMAX * 8];
__device__ int   g_srcE[BEMAX];           // per-edge src (global node id)
__device__ int   g_dstE[BEMAX];           // per-edge dst (global node id)
__device__ int   g_deg [BNMAX];           // per-node in-degree
__device__ int   g_cur [BNMAX];           // scatter cursors
__device__ int   g_off [BNMAX + 1];       // CSR row offsets
__device__ int   g_csr_src[BEMAX];        // CSR: src per edge slot
__device__ float g_csr_ea [BEMAX];        // CSR: edge attr per edge slot
__device__ float g_pool[MAXB * 11];       // per-graph pooled sums

__device__ __forceinline__ float lrelu(float x) { return fmaxf(x, 0.01f * x); }

// ---------------------------------------------------------------------------
// K0: build x0, layer-1 node projections (input dim 3), zero deg + pool
// ---------------------------------------------------------------------------
__global__ void k_prep(const int* __restrict__ nf, const float* __restrict__ act,
                       const float* __restrict__ W1, int BN) {
    int i = blockIdx.x * blockDim.x + threadIdx.x;
    if (i < MAXB * 11) g_pool[i] = 0.0f;
    if (i >= BN) return;
    g_deg[i] = 0;
    float x0 = (float)nf[2 * i];
    float x1 = (float)nf[2 * i + 1];
    float x2 = act[i];
    g_x0[3 * i]     = x0;
    g_x0[3 * i + 1] = x1;
    g_x0[3 * i + 2] = x2;
#pragma unroll
    for (int j = 0; j < 8; j++) {
        // W1 rows 0..2 -> x_dst part, rows 3..5 -> x_src part (row 6 = edge attr)
        g_pdA[8 * i + j] = fmaf(x0, __ldg(W1 + 0 * 8 + j),
                           fmaf(x1, __ldg(W1 + 1 * 8 + j),
                                x2 * __ldg(W1 + 2 * 8 + j)));
        g_psA[8 * i + j] = fmaf(x0, __ldg(W1 + 3 * 8 + j),
                           fmaf(x1, __ldg(W1 + 4 * 8 + j),
                                x2 * __ldg(W1 + 5 * 8 + j)));
    }
}

// ---------------------------------------------------------------------------
// K1: edge_index (int32) [B,2,E] -> src/dst with b*N baked in + degree hist
// ---------------------------------------------------------------------------
__global__ void k_conv(const int* __restrict__ ei, int B, int E, int N) {
    int e = blockIdx.x * blockDim.x + threadIdx.x;
    if (e >= B * E) return;
    int b = e / E;
    int k = e - b * E;
    int s = ei[b * 2 * E + k]     + b * N;
    int d = ei[b * 2 * E + E + k] + b * N;
    g_srcE[e] = s;
    g_dstE[e] = d;
    atomicAdd(&g_deg[d], 1);
}

// ---------------------------------------------------------------------------
// K2: exclusive scan of degrees -> CSR offsets + cursors (single block)
// ---------------------------------------------------------------------------
__global__ void k_scan(int BN) {
    __shared__ int s[1024];
    int t = threadIdx.x;
    int chunk = (BN + 1023) >> 10;
    int lo = t * chunk;
    int hi = min(lo + chunk, BN);
    int sum = 0;
    for (int i = lo; i < hi; i++) sum += g_deg[i];
    s[t] = sum;
    __syncthreads();
    // Hillis-Steele inclusive scan over 1024 partials
    for (int off = 1; off < 1024; off <<= 1) {
        int v = s[t];
        if (t >= off) v += s[t - off];
        __syncthreads();
        s[t] = v;
        __syncthreads();
    }
    int base = (t > 0) ? s[t - 1] : 0;
    for (int i = lo; i < hi; i++) {
        g_off[i] = base;
        g_cur[i] = base;
        base += g_deg[i];
    }
    if (t == 1023) g_off[BN] = base;
}

// ---------------------------------------------------------------------------
// K3: scatter edges into CSR slots (order within a node is irrelevant: min)
// ---------------------------------------------------------------------------
__global__ void k_scatter(const float* __restrict__ ea, int BE) {
    int e = blockIdx.x * blockDim.x + threadIdx.x;
    if (e >= BE) return;
    int d = g_dstE[e];
    int pos = atomicAdd(&g_cur[d], 1);
    g_csr_src[pos] = g_srcE[e];
    g_csr_ea[pos]  = ea[e];
}

// ---------------------------------------------------------------------------
// K4 (x3): warp-per-node gather. Per edge: 8-wide MLP + register min.
// b2 is folded out of the loop (min(b2+x) = b2+min(x)); pd[dst]+b1 hoisted.
// Lanes 0..7 then either write h (last layer) or next-layer projections.
// phase selects ping-pong buffers: 0 = read A write B, 1 = read B write A.
// ---------------------------------------------------------------------------
__global__ void k_gather(const float* __restrict__ crow,
                         const float* __restrict__ b1,
                         const float* __restrict__ W2,
                         const float* __restrict__ b2,
                         const float* __restrict__ W1n,
                         int phase, int last, int BN) {
    int warp = (blockIdx.x * blockDim.x + threadIdx.x) >> 5;
    int lane = threadIdx.x & 31;
    if (warp >= BN) return;

    const float* ps_in  = phase ? g_psB : g_psA;
    const float* pd_in  = phase ? g_pdB : g_pdA;
    float*       pd_out = phase ? g_pdA : g_pdB;
    float*       ps_out = phase ? g_psA : g_psB;

    float c[8], pdb[8], w2[64];
#pragma unroll
    for (int j = 0; j < 8; j++) {
        c[j]   = __ldg(crow + j);
        pdb[j] = pd_in[8 * warp + j] + __ldg(b1 + j);
    }
#pragma unroll
    for (int j = 0; j < 64; j++) w2[j] = __ldg(W2 + j);

    int start = g_off[warp];
    int end   = g_off[warp + 1];

    float acc[8];
#pragma unroll
    for (int j = 0; j < 8; j++) acc[j] = CUDART_INF_F;

    for (int e = start + lane; e < end; e += 32) {
        int   s   = g_csr_src[e];
        float eav = g_csr_ea[e];
        float4 p0 = *(const float4*)(ps_in + 8 * s);
        float4 p1 = *(const float4*)(ps_in + 8 * s + 4);
        float psv[8] = {p0.x, p0.y, p0.z, p0.w, p1.x, p1.y, p1.z, p1.w};

        float hid[8];
#pragma unroll
        for (int j = 0; j < 8; j++)
            hid[j] = lrelu(fmaf(c[j], eav, pdb[j] + psv[j]));

#pragma unroll
        for (int j = 0; j < 8; j++) {
            float o = 0.0f;
#pragma unroll
            for (int k = 0; k < 8; k++) o = fmaf(hid[k], w2[k * 8 + j], o);
            acc[j] = fminf(acc[j], o);
        }
    }

    // warp butterfly min (all lanes end with the full reduced vector)
#pragma unroll
    for (int off = 16; off > 0; off >>= 1) {
#pragma unroll
        for (int j = 0; j < 8; j++)
            acc[j] = fminf(acc[j], __shfl_xor_sync(0xffffffffu, acc[j], off));
    }

    float h[8];
#pragma unroll
    for (int j = 0; j < 8; j++) {
        // empty node -> 0, else add back b2; then outer LeakyReLU
        float v = (__float_as_uint(acc[j]) == 0x7f800000u)
                      ? 0.0f : (acc[j] + __ldg(b2 + j));
        h[j] = lrelu(v);
    }

    if (last) {
        if (lane < 8) pd_out[8 * warp + lane] = h[lane];
    } else if (lane < 8) {
        float a = 0.0f, bb = 0.0f;
#pragma unroll
        for (int k = 0; k < 8; k++) {
            a  = fmaf(h[k], __ldg(W1n + k * 8 + lane), a);
            bb = fmaf(h[k], __ldg(W1n + (8 + k) * 8 + lane), bb);
        }
        pd_out[8 * warp + lane] = a;
        ps_out[8 * warp + lane] = bb;
    }
}

// ---------------------------------------------------------------------------
// K5: sum-pool of [x0, h3] into g_pool (h3 lives in g_pdB after layer 3)
// ---------------------------------------------------------------------------
__global__ void k_final(int BN, int N) {
    __shared__ float s[2][11];  // a block can straddle at most 2 graphs
    int t = threadIdx.x;
    if (t < 22) ((float*)s)[t] = 0.0f;
    __syncthreads();

    int i  = blockIdx.x * blockDim.x + t;
    int b0 = (blockIdx.x * blockDim.x) / N;
    int B  = BN / N;
    if (i < BN) {
        int b = i / N;
        int slot = b - b0;
        float vals[11];
        vals[0] = g_x0[3 * i];
        vals[1] = g_x0[3 * i + 1];
        vals[2] = g_x0[3 * i + 2];
#pragma unroll
        for (int j = 0; j < 8; j++) vals[3 + j] = g_pdB[8 * i + j];
#pragma unroll
        for (int cc = 0; cc < 11; cc++) atomicAdd(&s[slot][cc], vals[cc]);
    }
    __syncthreads();
    if (t < 22) {
        int slot = t / 11, cc = t - slot * 11;
        int b = b0 + slot;
        if (b < B) atomicAdd(&g_pool[b * 11 + cc], s[slot][cc]);
    }
}

// ---------------------------------------------------------------------------
// K6: final linear  out[b] = pool[b] . lin_W + lin_b
// ---------------------------------------------------------------------------
__global__ void k_out(const float* __restrict__ linW, const float* __restrict__ linb,
                      float* __restrict__ out, int B) {
    int b = threadIdx.x;
    if (b < B) {
        float acc = __ldg(linb);
#pragma unroll
        for (int k = 0; k < 11; k++) acc = fmaf(g_pool[b * 11 + k], __ldg(linW + k), acc);
        out[b] = acc;
    }
}

extern "C" void kernel_launch(void* const* d_in, const int* in_sizes, int n_in,
                              void* d_out, int out_size) {
    const int*   nf   = (const int*)d_in[0];
    const float* act  = (const float*)d_in[1];
    const int*   ei   = (const int*)d_in[2];   // int32 (JAX x64 disabled)
    const float* ea   = (const float*)d_in[3];
    const float* c1W1 = (const float*)d_in[4];
    const float* c1b1 = (const float*)d_in[5];
    const float* c1W2 = (const float*)d_in[6];
    const float* c1b2 = (const float*)d_in[7];
    const float* c2W1 = (const float*)d_in[8];
    const float* c2b1 = (const float*)d_in[9];
    const float* c2W2 = (const float*)d_in[10];
    const float* c2b2 = (const float*)d_in[11];
    const float* c3W1 = (const float*)d_in[12];
    const float* c3b1 = (const float*)d_in[13];
    const float* c3W2 = (const float*)d_in[14];
    const float* c3b2 = (const float*)d_in[15];
    const float* linW = (const float*)d_in[16];
    const float* linb = (const float*)d_in[17];

    int B  = out_size;         // 4
    int BN = in_sizes[1];      // B*N = 80000
    int N  = BN / B;           // 20000
    int BE = in_sizes[3];      // B*E = 2560000
    int E  = BE / B;           // 640000

    int nb_node   = (BN + 255) / 256;
    int nb_edge   = (BE + 255) / 256;
    int nb_gather = (BN * 32 + 255) / 256;   // one warp per node

    k_prep   <<<nb_node, 256>>>(nf, act, c1W1, BN);
    k_conv   <<<nb_edge, 256>>>(ei, B, E, N);
    k_scan   <<<1, 1024>>>(BN);
    k_scatter<<<nb_edge, 256>>>(ea, BE);

    // layer 1 (input dim 3: edge-attr row = W1[6]); read A, write B
    k_gather<<<nb_gather, 256>>>(c1W1 + 6 * 8,  c1b1, c1W2, c1b2, c2W1, 0, 0, BN);
    // layer 2 (input dim 8: edge-attr row = W1[16]); read B, write A
    k_gather<<<nb_gather, 256>>>(c2W1 + 16 * 8, c2b1, c2W2, c2b2, c3W1, 1, 0, BN);
    // layer 3; read A, write h into B (pd part)
    k_gather<<<nb_gather, 256>>>(c3W1 + 16 * 8, c3b1, c3W2, c3b2, c3W1, 0, 1, BN);

    k_final<<<nb_node, 256>>>(BN, N);
    k_out  <<<1, 32>>>(linW, linb, (float*)d_out, B);
}

// round 8
// speedup vs baseline: 2.2082x; 2.2082x over previous
#include <cuda_runtime.h>
#include <math_constants.h>

// Problem sizes (fixed by the dataset): B=4, N=20000, E=640000, H=8
#define MAXB 4
#define MAXN 20000
#define MAXE 640000
#define BNMAX (MAXB * MAXN)
#define BEMAX (MAXB * MAXE)
#define NBLK  ((BNMAX + 255) / 256)   // 313

// Scratch (device globals; no dynamic allocation allowed)
__device__ float g_pdA[BNMAX * 8];        // node projections, buffer A (dst role)
__device__ float g_psA[BNMAX * 8];        //                            (src role)
__device__ float g_pdB[BNMAX * 8];        // buffer B
__device__ float g_psB[BNMAX * 8];
__device__ int   g_deg [BNMAX];           // per-node in-degree
__device__ int   g_cur [BNMAX];           // scatter cursors
__device__ int   g_off [BNMAX + 1];       // CSR row offsets
__device__ int   g_blk [NBLK];            // block sums for scan
__device__ int   g_blkoff[NBLK];          // exclusive block offsets
__device__ int2  g_csr [BEMAX];           // CSR entry: (src, ea-bits)
__device__ float g_pool[MAXB * 11];       // per-graph pooled sums

__device__ __forceinline__ float lrelu(float x) { return fmaxf(x, 0.01f * x); }

// ---------------------------------------------------------------------------
// K-1: zero the pooled sums (prep and last gather accumulate into them)
// ---------------------------------------------------------------------------
__global__ void k_zero() {
    int t = threadIdx.x;
    if (t < MAXB * 11) g_pool[t] = 0.0f;
}

// ---------------------------------------------------------------------------
// K0: layer-1 node projections (input dim 3), zero deg, pool x0 sums
// ---------------------------------------------------------------------------
__global__ void k_prep(const int* __restrict__ nf, const float* __restrict__ act,
                       const float* __restrict__ W1, int BN, int N) {
    __shared__ float s[2][3];            // block straddles at most 2 graphs
    int t = threadIdx.x;
    if (t < 6) ((float*)s)[t] = 0.0f;
    __syncthreads();

    int i  = blockIdx.x * blockDim.x + t;
    int b0 = (blockIdx.x * blockDim.x) / N;
    if (i < BN) {
        g_deg[i] = 0;
        float x0 = (float)nf[2 * i];
        float x1 = (float)nf[2 * i + 1];
        float x2 = act[i];
#pragma unroll
        for (int j = 0; j < 8; j++) {
            // W1 rows 0..2 -> dst part, rows 3..5 -> src part (row 6 = edge attr)
            g_pdA[8 * i + j] = fmaf(x0, __ldg(W1 + 0 * 8 + j),
                               fmaf(x1, __ldg(W1 + 1 * 8 + j),
                                    x2 * __ldg(W1 + 2 * 8 + j)));
            g_psA[8 * i + j] = fmaf(x0, __ldg(W1 + 3 * 8 + j),
                               fmaf(x1, __ldg(W1 + 4 * 8 + j),
                                    x2 * __ldg(W1 + 5 * 8 + j)));
        }
        int slot = i / N - b0;
        atomicAdd(&s[slot][0], x0);
        atomicAdd(&s[slot][1], x1);
        atomicAdd(&s[slot][2], x2);
    }
    __syncthreads();
    if (t < 6) {
        int slot = t / 3, cc = t - slot * 3;
        int b = b0 + slot;
        if (b < BN / N) atomicAdd(&g_pool[b * 11 + cc], s[slot][cc]);
    }
}

// ---------------------------------------------------------------------------
// K1: in-degree histogram (reads only the dst half of edge_index [B,2,E])
// ---------------------------------------------------------------------------
__global__ void k_hist(const int* __restrict__ ei, int B, int E, int N) {
    int e = blockIdx.x * blockDim.x + threadIdx.x;
    if (e >= B * E) return;
    int b = e / E;
    int k = e - b * E;
    int d = ei[b * 2 * E + E + k] + b * N;
    atomicAdd(&g_deg[d], 1);
}

// ---------------------------------------------------------------------------
// K2a/K2b/K2c: coalesced 3-phase exclusive scan of degrees -> CSR offsets
// ---------------------------------------------------------------------------
__global__ void k_scan1(int BN) {
    __shared__ int s[256];
    int t = threadIdx.x;
    int i = blockIdx.x * 256 + t;
    s[t] = (i < BN) ? g_deg[i] : 0;
    __syncthreads();
#pragma unroll
    for (int off = 128; off > 0; off >>= 1) {
        if (t < off) s[t] += s[t + off];
        __syncthreads();
    }
    if (t == 0) g_blk[blockIdx.x] = s[0];
}

__global__ void k_scan2(int nblk, int BN) {
    __shared__ int s[512];
    int t = threadIdx.x;
    int v = (t < nblk) ? g_blk[t] : 0;
    s[t] = v;
    __syncthreads();
#pragma unroll
    for (int off = 1; off < 512; off <<= 1) {
        int x = s[t];
        if (t >= off) x += s[t - off];
        __syncthreads();
        s[t] = x;
        __syncthreads();
    }
    if (t < nblk) g_blkoff[t] = s[t] - v;          // exclusive
    if (t == nblk - 1) g_off[BN] = s[t];           // total edge count
}

__global__ void k_scan3(int BN) {
    __shared__ int s[256];
    int t = threadIdx.x;
    int i = blockIdx.x * 256 + t;
    int d = (i < BN) ? g_deg[i] : 0;
    s[t] = d;
    __syncthreads();
#pragma unroll
    for (int off = 1; off < 256; off <<= 1) {
        int x = s[t];
        if (t >= off) x += s[t - off];
        __syncthreads();
        s[t] = x;
        __syncthreads();
    }
    if (i < BN) {
        int off = g_blkoff[blockIdx.x] + s[t] - d;  // exclusive global offset
        g_off[i] = off;
        g_cur[i] = off;
    }
}

// ---------------------------------------------------------------------------
// K3: scatter edges into CSR slots as packed (src, ea) int2.
// Slot order within a node is irrelevant: exact-float min is commutative.
// ---------------------------------------------------------------------------
__global__ void k_scatter(const int* __restrict__ ei, const float* __restrict__ ea,
                          int B, int E, int N) {
    int e = blockIdx.x * blockDim.x + threadIdx.x;
    if (e >= B * E) return;
    int b = e / E;
    int k = e - b * E;
    int s = ei[b * 2 * E + k]     + b * N;
    int d = ei[b * 2 * E + E + k] + b * N;
    int pos = atomicAdd(&g_cur[d], 1);
    g_csr[pos] = make_int2(s, __float_as_int(ea[e]));
}

// ---------------------------------------------------------------------------
// K4 (x3): 8-lanes-per-node gather. Per edge: 8-wide MLP + register min.
// b2 folded out of the min; pd[dst]+b1 hoisted per node. 3-step butterfly.
// phase: 0 = read A write B, 1 = read B write A. last: pool h sums instead
// of computing next-layer projections.
// ---------------------------------------------------------------------------
__global__ void k_gather(const float* __restrict__ crow,
                         const float* __restrict__ b1,
                         const float* __restrict__ W2,
                         const float* __restrict__ b2,
                         const float* __restrict__ W1n,
                         int phase, int last, int BN, int N) {
    __shared__ float spool[2][8];
    int t = threadIdx.x;
    if (last && t < 16) ((float*)spool)[t] = 0.0f;
    if (last) __syncthreads();

    int tid  = blockIdx.x * blockDim.x + t;
    int node = tid >> 3;
    int l8   = t & 7;
    bool active = node < BN;

    const float* ps_in  = phase ? g_psB : g_psA;
    const float* pd_in  = phase ? g_pdB : g_pdA;
    float*       pd_out = phase ? g_pdA : g_pdB;
    float*       ps_out = phase ? g_psA : g_psB;

    float c[8], pdb[8], w2[64];
#pragma unroll
    for (int j = 0; j < 8; j++) c[j] = __ldg(crow + j);
#pragma unroll
    for (int j = 0; j < 64; j++) w2[j] = __ldg(W2 + j);

    int start = 0, end = 0;
    if (active) {
        start = g_off[node];
        end   = g_off[node + 1];
#pragma unroll
        for (int j = 0; j < 8; j++)
            pdb[j] = pd_in[8 * node + j] + __ldg(b1 + j);
    }

    float acc[8];
#pragma unroll
    for (int j = 0; j < 8; j++) acc[j] = CUDART_INF_F;

    for (int e = start + l8; e < end; e += 8) {
        int2  pr  = __ldg(&g_csr[e]);
        int   s   = pr.x;
        float eav = __int_as_float(pr.y);
        float4 p0 = *(const float4*)(ps_in + 8 * s);
        float4 p1 = *(const float4*)(ps_in + 8 * s + 4);
        float psv[8] = {p0.x, p0.y, p0.z, p0.w, p1.x, p1.y, p1.z, p1.w};

        float hid[8];
#pragma unroll
        for (int j = 0; j < 8; j++)
            hid[j] = lrelu(fmaf(c[j], eav, pdb[j] + psv[j]));

#pragma unroll
        for (int j = 0; j < 8; j++) {
            float o = 0.0f;
#pragma unroll
            for (int k = 0; k < 8; k++) o = fmaf(hid[k], w2[k * 8 + j], o);
            acc[j] = fminf(acc[j], o);
        }
    }

    // butterfly min over the 8-lane group (groups are xor-aligned within warp)
#pragma unroll
    for (int off = 4; off > 0; off >>= 1) {
#pragma unroll
        for (int j = 0; j < 8; j++)
            acc[j] = fminf(acc[j], __shfl_xor_sync(0xffffffffu, acc[j], off));
    }

    float h[8];
#pragma unroll
    for (int j = 0; j < 8; j++) {
        // empty node -> 0, else add back b2; then outer LeakyReLU
        float v = (__float_as_uint(acc[j]) == 0x7f800000u)
                      ? 0.0f : (acc[j] + __ldg(b2 + j));
        h[j] = lrelu(v);
    }

    if (!last) {
        if (active) {
            // lane j computes next-layer projection column j
            float a = 0.0f, bb = 0.0f;
#pragma unroll
            for (int k = 0; k < 8; k++) {
                a  = fmaf(h[k], __ldg(W1n + k * 8 + l8), a);
                bb = fmaf(h[k], __ldg(W1n + (8 + k) * 8 + l8), bb);
            }
            pd_out[8 * node + l8] = a;
            ps_out[8 * node + l8] = bb;
        }
    } else {
        // pool h sums per graph via shared accumulation
        int node0 = blockIdx.x * (blockDim.x >> 3);
        int b0 = node0 / N;
        if (active) {
            int slot = node / N - b0;
            atomicAdd(&spool[slot][l8], h[l8]);
        }
        __syncthreads();
        if (t < 16) {
            int slot = t >> 3, j = t & 7;
            int b = b0 + slot;
            if (b < BN / N) atomicAdd(&g_pool[b * 11 + 3 + j], spool[slot][j]);
        }
    }
}

// ---------------------------------------------------------------------------
// K5: final linear  out[b] = pool[b] . lin_W + lin_b
// ---------------------------------------------------------------------------
__global__ void k_out(const float* __restrict__ linW, const float* __restrict__ linb,
                      float* __restrict__ out, int B) {
    int b = threadIdx.x;
    if (b < B) {
        float acc = __ldg(linb);
#pragma unroll
        for (int k = 0; k < 11; k++) acc = fmaf(g_pool[b * 11 + k], __ldg(linW + k), acc);
        out[b] = acc;
    }
}

extern "C" void kernel_launch(void* const* d_in, const int* in_sizes, int n_in,
                              void* d_out, int out_size) {
    const int*   nf   = (const int*)d_in[0];
    const float* act  = (const float*)d_in[1];
    const int*   ei   = (const int*)d_in[2];   // int32 (JAX x64 disabled)
    const float* ea   = (const float*)d_in[3];
    const float* c1W1 = (const float*)d_in[4];
    const float* c1b1 = (const float*)d_in[5];
    const float* c1W2 = (const float*)d_in[6];
    const float* c1b2 = (const float*)d_in[7];
    const float* c2W1 = (const float*)d_in[8];
    const float* c2b1 = (const float*)d_in[9];
    const float* c2W2 = (const float*)d_in[10];
    const float* c2b2 = (const float*)d_in[11];
    const float* c3W1 = (const float*)d_in[12];
    const float* c3b1 = (const float*)d_in[13];
    const float* c3W2 = (const float*)d_in[14];
    const float* c3b2 = (const float*)d_in[15];
    const float* linW = (const float*)d_in[16];
    const float* linb = (const float*)d_in[17];

    int B  = out_size;         // 4
    int BN = in_sizes[1];      // B*N = 80000
    int N  = BN / B;           // 20000
    int BE = in_sizes[3];      // B*E = 2560000
    int E  = BE / B;           // 640000

    int nb_node   = (BN + 255) / 256;        // 313
    int nb_edge   = (BE + 255) / 256;
    int nb_gather = (BN * 8 + 255) / 256;    // 8 lanes per node -> 2500

    k_zero   <<<1, 64>>>();
    k_prep   <<<nb_node, 256>>>(nf, act, c1W1, BN, N);
    k_hist   <<<nb_edge, 256>>>(ei, B, E, N);
    k_scan1  <<<nb_node, 256>>>(BN);
    k_scan2  <<<1, 512>>>(nb_node, BN);
    k_scan3  <<<nb_node, 256>>>(BN);
    k_scatter<<<nb_edge, 256>>>(ei, ea, B, E, N);

    // layer 1 (input dim 3: edge-attr row = W1[6]); read A, write B
    k_gather<<<nb_gather, 256>>>(c1W1 + 6 * 8,  c1b1, c1W2, c1b2, c2W1, 0, 0, BN, N);
    // layer 2 (input dim 8: edge-attr row = W1[16]); read B, write A
    k_gather<<<nb_gather, 256>>>(c2W1 + 16 * 8, c2b1, c2W2, c2b2, c3W1, 1, 0, BN, N);
    // layer 3; read A, pool h directly
    k_gather<<<nb_gather, 256>>>(c3W1 + 16 * 8, c3b1, c3W2, c3b2, c3W1, 0, 1, BN, N);

    k_out<<<1, 32>>>(linW, linb, (float*)d_out, B);
}

// round 9
// speedup vs baseline: 2.4380x; 1.1040x over previous
#include <cuda_runtime.h>
#include <math_constants.h>

// Problem sizes (fixed by the dataset): B=4, N=20000, E=640000, H=8
#define MAXB 4
#define MAXN 20000
#define MAXE 640000
#define BNMAX (MAXB * MAXN)
#define BEMAX (MAXB * MAXE)
#define NBLK  ((BNMAX + 255) / 256)   // 313

// Scratch (device globals; no dynamic allocation allowed)
__device__ float g_pdA[BNMAX * 8];        // node projections, buffer A (dst role)
__device__ float g_psA[BNMAX * 8];        //                            (src role)
__device__ float g_pdB[BNMAX * 8];        // buffer B
__device__ float g_psB[BNMAX * 8];
__device__ int   g_deg [BNMAX];           // per-node in-degree
__device__ int   g_rank[BEMAX];           // per-edge rank within its dst bucket
__device__ int   g_off [BNMAX + 1];       // CSR row offsets
__device__ int   g_blk [NBLK];            // block sums for scan
__device__ int   g_blkoff[NBLK];          // exclusive block offsets
__device__ int2  g_csr [BEMAX];           // CSR entry: (src, ea-bits)
__device__ float g_pool[MAXB * 11];       // per-graph pooled sums

__device__ __forceinline__ float lrelu(float x) { return fmaxf(x, 0.01f * x); }

// ---------------------------------------------------------------------------
// K0: layer-1 node projections (input dim 3), zero deg+pool, pool x0 sums
// ---------------------------------------------------------------------------
__global__ void k_prep(const int* __restrict__ nf, const float* __restrict__ act,
                       const float* __restrict__ W1, int BN, int N) {
    __shared__ float s[2][3];            // block straddles at most 2 graphs
    int t = threadIdx.x;
    if (t < 6) ((float*)s)[t] = 0.0f;
    __syncthreads();

    int i  = blockIdx.x * blockDim.x + t;
    int b0 = (blockIdx.x * blockDim.x) / N;
    if (i < MAXB * 11) g_pool[i] = 0.0f;
    if (i < BN) {
        g_deg[i] = 0;
        float x0 = (float)nf[2 * i];
        float x1 = (float)nf[2 * i + 1];
        float x2 = act[i];
#pragma unroll
        for (int j = 0; j < 8; j++) {
            // W1 rows 0..2 -> dst part, rows 3..5 -> src part (row 6 = edge attr)
            g_pdA[8 * i + j] = fmaf(x0, __ldg(W1 + 0 * 8 + j),
                               fmaf(x1, __ldg(W1 + 1 * 8 + j),
                                    x2 * __ldg(W1 + 2 * 8 + j)));
            g_psA[8 * i + j] = fmaf(x0, __ldg(W1 + 3 * 8 + j),
                               fmaf(x1, __ldg(W1 + 4 * 8 + j),
                                    x2 * __ldg(W1 + 5 * 8 + j)));
        }
        int slot = i / N - b0;
        atomicAdd(&s[slot][0], x0);
        atomicAdd(&s[slot][1], x1);
        atomicAdd(&s[slot][2], x2);
    }
    __syncthreads();
    if (t < 6) {
        int slot = t / 3, cc = t - slot * 3;
        int b = b0 + slot;
        if (b < BN / N) atomicAdd(&g_pool[b * 11 + cc], s[slot][cc]);
    }
}

// ---------------------------------------------------------------------------
// K1: in-degree histogram; the atomic's return value is this edge's rank
// within its dst bucket (stored coalesced for the atomic-free scatter).
// ---------------------------------------------------------------------------
__global__ void k_hist(const int* __restrict__ ei, int B, int E, int N) {
    int e = blockIdx.x * blockDim.x + threadIdx.x;
    if (e >= B * E) return;
    int b = e / E;
    int k = e - b * E;
    int d = ei[b * 2 * E + E + k] + b * N;
    g_rank[e] = atomicAdd(&g_deg[d], 1);
}

// ---------------------------------------------------------------------------
// K2a/K2b/K2c: coalesced 3-phase exclusive scan of degrees -> CSR offsets
// ---------------------------------------------------------------------------
__global__ void k_scan1(int BN) {
    __shared__ int s[256];
    int t = threadIdx.x;
    int i = blockIdx.x * 256 + t;
    s[t] = (i < BN) ? g_deg[i] : 0;
    __syncthreads();
#pragma unroll
    for (int off = 128; off > 0; off >>= 1) {
        if (t < off) s[t] += s[t + off];
        __syncthreads();
    }
    if (t == 0) g_blk[blockIdx.x] = s[0];
}

__global__ void k_scan2(int nblk, int BN) {
    __shared__ int s[512];
    int t = threadIdx.x;
    int v = (t < nblk) ? g_blk[t] : 0;
    s[t] = v;
    __syncthreads();
#pragma unroll
    for (int off = 1; off < 512; off <<= 1) {
        int x = s[t];
        if (t >= off) x += s[t - off];
        __syncthreads();
        s[t] = x;
        __syncthreads();
    }
    if (t < nblk) g_blkoff[t] = s[t] - v;          // exclusive
    if (t == nblk - 1) g_off[BN] = s[t];           // total edge count
}

__global__ void k_scan3(int BN) {
    __shared__ int s[256];
    int t = threadIdx.x;
    int i = blockIdx.x * 256 + t;
    int d = (i < BN) ? g_deg[i] : 0;
    s[t] = d;
    __syncthreads();
#pragma unroll
    for (int off = 1; off < 256; off <<= 1) {
        int x = s[t];
        if (t >= off) x += s[t - off];
        __syncthreads();
        s[t] = x;
        __syncthreads();
    }
    if (i < BN) g_off[i] = g_blkoff[blockIdx.x] + s[t] - d;  // exclusive
}

// ---------------------------------------------------------------------------
// K3: atomic-free scatter: pos = off[dst] + rank[e]; one 8B random store.
// Slot order within a node is irrelevant: exact-float min is commutative.
// ---------------------------------------------------------------------------
__global__ void k_scatter(const int* __restrict__ ei, const float* __restrict__ ea,
                          int B, int E, int N) {
    int e = blockIdx.x * blockDim.x + threadIdx.x;
    if (e >= B * E) return;
    int b = e / E;
    int k = e - b * E;
    int s = ei[b * 2 * E + k]     + b * N;
    int d = ei[b * 2 * E + E + k] + b * N;
    int pos = g_off[d] + g_rank[e];
    g_csr[pos] = make_int2(s, __float_as_int(ea[e]));
}

// ---------------------------------------------------------------------------
// K4 (x3): 8-lanes-per-node gather, 2-edge unrolled for load ILP.
// b2 folded out of the min; pd[dst]+b1 hoisted per node. 3-step butterfly.
// phase: 0 = read A write B, 1 = read B write A. last: pool h sums instead
// of computing next-layer projections.
// ---------------------------------------------------------------------------
__global__ void k_gather(const float* __restrict__ crow,
                         const float* __restrict__ b1,
                         const float* __restrict__ W2,
                         const float* __restrict__ b2,
                         const float* __restrict__ W1n,
                         int phase, int last, int BN, int N) {
    __shared__ float spool[2][8];
    int t = threadIdx.x;
    if (last && t < 16) ((float*)spool)[t] = 0.0f;
    if (last) __syncthreads();

    int tid  = blockIdx.x * blockDim.x + t;
    int node = tid >> 3;
    int l8   = t & 7;
    bool active = node < BN;

    const float* ps_in  = phase ? g_psB : g_psA;
    const float* pd_in  = phase ? g_pdB : g_pdA;
    float*       pd_out = phase ? g_pdA : g_pdB;
    float*       ps_out = phase ? g_psA : g_psB;

    float c[8], pdb[8], w2[64];
#pragma unroll
    for (int j = 0; j < 8; j++) c[j] = __ldg(crow + j);
#pragma unroll
    for (int j = 0; j < 64; j++) w2[j] = __ldg(W2 + j);

    int start = 0, end = 0;
    if (active) {
        start = __ldg(&g_off[node]);
        end   = __ldg(&g_off[node + 1]);
#pragma unroll
        for (int j = 0; j < 8; j++)
            pdb[j] = pd_in[8 * node + j] + __ldg(b1 + j);
    }

    float acc[8];
#pragma unroll
    for (int j = 0; j < 8; j++) acc[j] = CUDART_INF_F;

    for (int e = start + l8; e < end; e += 16) {
        bool has2 = (e + 8) < end;
        int2 pr0 = __ldg(&g_csr[e]);
        int2 pr1 = has2 ? __ldg(&g_csr[e + 8]) : pr0;

        // issue both gathers before any arithmetic (hide L2 latency)
        float4 a0 = *(const float4*)(ps_in + 8 * pr0.x);
        float4 a1 = *(const float4*)(ps_in + 8 * pr0.x + 4);
        float4 b0 = *(const float4*)(ps_in + 8 * pr1.x);
        float4 b1v = *(const float4*)(ps_in + 8 * pr1.x + 4);

        float ea0 = __int_as_float(pr0.y);
        float ea1 = __int_as_float(pr1.y);
        float ps0[8] = {a0.x, a0.y, a0.z, a0.w, a1.x, a1.y, a1.z, a1.w};
        float ps1[8] = {b0.x, b0.y, b0.z, b0.w, b1v.x, b1v.y, b1v.z, b1v.w};

        float h0[8], h1[8];
#pragma unroll
        for (int j = 0; j < 8; j++) {
            h0[j] = lrelu(fmaf(c[j], ea0, pdb[j] + ps0[j]));
            h1[j] = lrelu(fmaf(c[j], ea1, pdb[j] + ps1[j]));
        }

#pragma unroll
        for (int j = 0; j < 8; j++) {
            float o0 = 0.0f, o1 = 0.0f;
#pragma unroll
            for (int k = 0; k < 8; k++) {
                o0 = fmaf(h0[k], w2[k * 8 + j], o0);
                o1 = fmaf(h1[k], w2[k * 8 + j], o1);
            }
            acc[j] = fminf(acc[j], o0);
            if (has2) acc[j] = fminf(acc[j], o1);
        }
    }

    // butterfly min over the 8-lane group (groups are xor-aligned within warp)
#pragma unroll
    for (int off = 4; off > 0; off >>= 1) {
#pragma unroll
        for (int j = 0; j < 8; j++)
            acc[j] = fminf(acc[j], __shfl_xor_sync(0xffffffffu, acc[j], off));
    }

    float h[8];
#pragma unroll
    for (int j = 0; j < 8; j++) {
        // empty node -> 0, else add back b2; then outer LeakyReLU
        float v = (__float_as_uint(acc[j]) == 0x7f800000u)
                      ? 0.0f : (acc[j] + __ldg(b2 + j));
        h[j] = lrelu(v);
    }

    if (!last) {
        if (active) {
            // lane j computes next-layer projection column j
            float a = 0.0f, bb = 0.0f;
#pragma unroll
            for (int k = 0; k < 8; k++) {
                a  = fmaf(h[k], __ldg(W1n + k * 8 + l8), a);
                bb = fmaf(h[k], __ldg(W1n + (8 + k) * 8 + l8), bb);
            }
            pd_out[8 * node + l8] = a;
            ps_out[8 * node + l8] = bb;
        }
    } else {
        // pool h sums per graph via shared accumulation
        int node0 = blockIdx.x * (blockDim.x >> 3);
        int b0 = node0 / N;
        if (active) {
            int slot = node / N - b0;
            atomicAdd(&spool[slot][l8], h[l8]);
        }
        __syncthreads();
        if (t < 16) {
            int slot = t >> 3, j = t & 7;
            int b = b0 + slot;
            if (b < BN / N) atomicAdd(&g_pool[b * 11 + 3 + j], spool[slot][j]);
        }
    }
}

// ---------------------------------------------------------------------------
// K5: final linear  out[b] = pool[b] . lin_W + lin_b
// ---------------------------------------------------------------------------
__global__ void k_out(const float* __restrict__ linW, const float* __restrict__ linb,
                      float* __restrict__ out, int B) {
    int b = threadIdx.x;
    if (b < B) {
        float acc = __ldg(linb);
#pragma unroll
        for (int k = 0; k < 11; k++) acc = fmaf(g_pool[b * 11 + k], __ldg(linW + k), acc);
        out[b] = acc;
    }
}

extern "C" void kernel_launch(void* const* d_in, const int* in_sizes, int n_in,
                              void* d_out, int out_size) {
    const int*   nf   = (const int*)d_in[0];
    const float* act  = (const float*)d_in[1];
    const int*   ei   = (const int*)d_in[2];   // int32 (JAX x64 disabled)
    const float* ea   = (const float*)d_in[3];
    const float* c1W1 = (const float*)d_in[4];
    const float* c1b1 = (const float*)d_in[5];
    const float* c1W2 = (const float*)d_in[6];
    const float* c1b2 = (const float*)d_in[7];
    const float* c2W1 = (const float*)d_in[8];
    const float* c2b1 = (const float*)d_in[9];
    const float* c2W2 = (const float*)d_in[10];
    const float* c2b2 = (const float*)d_in[11];
    const float* c3W1 = (const float*)d_in[12];
    const float* c3b1 = (const float*)d_in[13];
    const float* c3W2 = (const float*)d_in[14];
    const float* c3b2 = (const float*)d_in[15];
    const float* linW = (const float*)d_in[16];
    const float* linb = (const float*)d_in[17];

    int B  = out_size;         // 4
    int BN = in_sizes[1];      // B*N = 80000
    int N  = BN / B;           // 20000
    int BE = in_sizes[3];      // B*E = 2560000
    int E  = BE / B;           // 640000

    int nb_node   = (BN + 255) / 256;        // 313
    int nb_edge   = (BE + 255) / 256;
    int nb_gather = (BN * 8 + 255) / 256;    // 8 lanes per node -> 2500

    k_prep   <<<nb_node, 256>>>(nf, act, c1W1, BN, N);
    k_hist   <<<nb_edge, 256>>>(ei, B, E, N);
    k_scan1  <<<nb_node, 256>>>(BN);
    k_scan2  <<<1, 512>>>(nb_node, BN);
    k_scan3  <<<nb_node, 256>>>(BN);
    k_scatter<<<nb_edge, 256>>>(ei, ea, B, E, N);

    // layer 1 (input dim 3: edge-attr row = W1[6]); read A, write B
    k_gather<<<nb_gather, 256>>>(c1W1 + 6 * 8,  c1b1, c1W2, c1b2, c2W1, 0, 0, BN, N);
    // layer 2 (input dim 8: edge-attr row = W1[16]); read B, write A
    k_gather<<<nb_gather, 256>>>(c2W1 + 16 * 8, c2b1, c2W2, c2b2, c3W1, 1, 0, BN, N);
    // layer 3; read A, pool h directly
    k_gather<<<nb_gather, 256>>>(c3W1 + 16 * 8, c3b1, c3W2, c3b2, c3W1, 0, 1, BN, N);

    k_out<<<1, 32>>>(linW, linb, (float*)d_out, B);
}